// round 13
// baseline (speedup 1.0000x reference)
#include <cuda_runtime.h>
#include <cuda_bf16.h>
#include <cstdint>

// ---------------------------------------------------------------------------
// STARDNN on GB300. R13 = R12 GEMM byte-identical; scaffolding only:
//  - launch order: scale_all, countscan(fused), scatter, g0, g1, g2
//    (6 launches; position #4 = gemm0 so ncu's capture slot hits a GEMM)
//  - live-tile grid via per-scene tile prefix (no dead CTAs)
// ---------------------------------------------------------------------------

#define NS    7
#define MAXB  16384
#define D0    512
#define D1    512
#define D2    256
#define D3    64

// scratch (allocation-free: __device__ globals)
__device__ int   g_count[NS];
__device__ int   g_offset[NS];
__device__ int   g_cursor[NS];
__device__ int   g_tile128[NS + 1];   // tile prefix for BM=128
__device__ int   g_tile64[NS + 1];    // tile prefix for BM=64
__device__ int   g_perm[MAXB];
__device__ float g_h1[MAXB * D1];
__device__ float g_h2[MAXB * D2];
__device__ float g_SW0[NS * D0 * D1];
__device__ float g_SW1[NS * D1 * D2];
__device__ float g_SW2[NS * D2 * D3];

// ------------------------------ helpers ------------------------------------
#define MMA_BF16(d, a, b) \
    asm volatile("mma.sync.aligned.m16n8k16.row.col.f32.bf16.bf16.f32 " \
                 "{%0,%1,%2,%3}, {%4,%5,%6,%7}, {%8,%9}, {%0,%1,%2,%3};" \
                 : "+f"((d)[0]), "+f"((d)[1]), "+f"((d)[2]), "+f"((d)[3]) \
                 : "r"((a)[0]), "r"((a)[1]), "r"((a)[2]), "r"((a)[3]), \
                   "r"((b)[0]), "r"((b)[1]))

__device__ __forceinline__ void bsplit(float v, __nv_bfloat16& h, __nv_bfloat16& l) {
    h = __float2bfloat16(v);
    l = __float2bfloat16(v - __bfloat162float(h));
}

__device__ __forceinline__ uint32_t pack2(__nv_bfloat16 a, __nv_bfloat16 b) {
    union { __nv_bfloat16 h[2]; uint32_t u; } t;
    t.h[0] = a; t.h[1] = b;
    return t.u;
}

// split a float4 into hi/lo packed uint2 (n-adjacent pairs; for A staging)
__device__ __forceinline__ void split4(float4 v, uint2& hi, uint2& lo) {
    __nv_bfloat16 h0, l0, h1, l1, h2, l2, h3, l3;
    bsplit(v.x, h0, l0); bsplit(v.y, h1, l1);
    bsplit(v.z, h2, l2); bsplit(v.w, h3, l3);
    hi.x = pack2(h0, h1); hi.y = pack2(h2, h3);
    lo.x = pack2(l0, l1); lo.y = pack2(l2, l3);
}

// pack two k-adjacent rows (same 4 n's) into k-pair words (for B staging)
__device__ __forceinline__ void packk4(float4 f0, float4 f1, uint4& hi, uint4& lo) {
    __nv_bfloat16 ha, la, hb, lb;
    bsplit(f0.x, ha, la); bsplit(f1.x, hb, lb);
    hi.x = pack2(ha, hb); lo.x = pack2(la, lb);
    bsplit(f0.y, ha, la); bsplit(f1.y, hb, lb);
    hi.y = pack2(ha, hb); lo.y = pack2(la, lb);
    bsplit(f0.z, ha, la); bsplit(f1.z, hb, lb);
    hi.z = pack2(ha, hb); lo.z = pack2(la, lb);
    bsplit(f0.w, ha, la); bsplit(f1.w, hb, lb);
    hi.w = pack2(ha, hb); lo.w = pack2(la, lb);
}

// ------------------------------ bucketing ----------------------------------
__device__ __forceinline__ int scene_at(const int* __restrict__ p, int b, bool is64) {
    int v = is64 ? p[2 * b] : p[b];
    int s = v - 1;
    return (s < 0) ? 0 : (s >= NS ? NS - 1 : s);
}

// fused init + count + scan + tile-prefix: single CTA, deterministic
__global__ __launch_bounds__(256) void k_countscan(const int* __restrict__ scene, int B) {
    __shared__ int hist[NS];
    if (threadIdx.x < NS) hist[threadIdx.x] = 0;
    __syncthreads();
    bool is64 = (scene[1] == 0);
    for (int b = threadIdx.x; b < B; b += 256)
        atomicAdd(&hist[scene_at(scene, b, is64)], 1);
    __syncthreads();
    if (threadIdx.x == 0) {
        int off = 0, t128 = 0, t64 = 0;
        for (int s = 0; s < NS; s++) {
            int c = hist[s];
            g_count[s] = c;
            g_offset[s] = off;
            g_cursor[s] = off;
            g_tile128[s] = t128;
            g_tile64[s] = t64;
            off += c;
            t128 += (c + 127) >> 7;
            t64  += (c + 63) >> 6;
        }
        g_tile128[NS] = t128;
        g_tile64[NS] = t64;
    }
}

__global__ void k_scatter(const int* __restrict__ scene, int B) {
    int b = blockIdx.x * blockDim.x + threadIdx.x;
    if (b < B) {
        bool is64 = (scene[1] == 0);
        int s = scene_at(scene, b, is64);
        int pos = atomicAdd(&g_cursor[s], 1);
        g_perm[pos] = b;
    }
}

// Pre-scale all weights (proven): SW[s][k][n] = W[s][k][n] * gW[k][n]
__global__ void k_scale_all(const float* __restrict__ W0, const float* __restrict__ gW0,
                            const float* __restrict__ W1, const float* __restrict__ gW1,
                            const float* __restrict__ W2, const float* __restrict__ gW2) {
    int stride = gridDim.x * blockDim.x;
    int t = blockIdx.x * blockDim.x + threadIdx.x;
    for (int j = t; j < D0 * D1; j += stride) {
        float g = gW0[j];
#pragma unroll
        for (int s = 0; s < NS; s++) g_SW0[s * D0 * D1 + j] = W0[s * D0 * D1 + j] * g;
    }
    for (int j = t; j < D1 * D2; j += stride) {
        float g = gW1[j];
#pragma unroll
        for (int s = 0; s < NS; s++) g_SW1[s * D1 * D2 + j] = W1[s * D1 * D2 + j] * g;
    }
    for (int j = t; j < D2 * D3; j += stride) {
        float g = gW2[j];
#pragma unroll
        for (int s = 0; s < NS; s++) g_SW2[s * D2 * D3 + j] = W2[s * D2 * D3 + j] * g;
    }
}

// ------------------------------ mma GEMM (R12 core, live-tile grid) --------
template <int LAYER, int K, int NF, int BM, int BN, bool RELU>
__global__ __launch_bounds__(256, 2) void k_gemm(const float* __restrict__ xin,
                                                 float* __restrict__ xout,
                                                 const float* __restrict__ bias,
                                                 const float* __restrict__ gbias,
                                                 int B) {
    constexpr int MI = BM / 2 / 16;       // m16 tiles per warp (4 or 2)
    constexpr int NI = BN / 4 / 8;        // n8 tiles per warp
    constexpr int NCH = K / 16;
    constexpr int ROWB = 48;
    constexpr int APL = BM * ROWB;
    constexpr int BROWW = BN + 8;         // words; == 8 mod 32
    constexpr int BROWB = BROWW * 4;
    constexpr int BPLP = 8 * BROWB;       // one B plane (8 k-pair rows)
    constexpr int BUFSZ = 2 * APL + 2 * BPLP;
    constexpr int APT = BM / 64;          // A float4 loads per thread (2 or 1)
    constexpr int BSLOTS = 8 * (BN / 4);  // B (k2, nquad) slots per chunk

    extern __shared__ char sm[];

    // live-tile lookup: scene from tile prefix
    const int* tstart = (BM == 128) ? g_tile128 : g_tile64;
    const int t = blockIdx.x;
    if (t >= tstart[NS]) return;
    int s = 0;
    while (tstart[s + 1] <= t) s++;
    const int m0   = (t - tstart[s]) * BM;
    const int cnt  = g_count[s];
    const int off  = g_offset[s];
    const int rows = min(BM, cnt - m0);
    const int n0   = blockIdx.y * BN;
    const int tid  = threadIdx.x;

    const float* in = (LAYER == 0) ? xin : (LAYER == 1 ? g_h1 : g_h2);
    float*      out = (LAYER == 2) ? xout : (LAYER == 0 ? g_h1 : g_h2);
    const float* SW = (LAYER == 0) ? g_SW0 : (LAYER == 1 ? g_SW1 : g_SW2);

    // ---- A staging (proven): APT float4 per thread per chunk ----
    const int aq = (tid & 3) * 4;                        // float col 0,4,8,12
    const float* aptr[APT];
    uint32_t adst[APT];
#pragma unroll
    for (int i = 0; i < APT; i++) {
        int r = (tid >> 2) + i * 64;
        int pr = off + m0 + ((r < rows) ? r : 0);        // clamp dead rows
        if (pr > B - 1) pr = B - 1;
        int grow = (LAYER == 0) ? g_perm[pr] : pr;
        aptr[i] = in + (size_t)grow * K + aq;
        adst[i] = (uint32_t)r * ROWB + aq * 2;
    }
    // ---- B staging: one (k-pair, n-quad) slot per active thread ----
    const bool bact = (tid < BSLOTS);
    const float* bptr0 = nullptr;                        // k row 2*k2
    uint32_t bdst = 0;
    if (bact) {
        int k2 = tid / (BN / 4);                         // 0..7
        int ncol = (tid % (BN / 4)) * 4;
        bptr0 = SW + ((size_t)s * K + 2 * k2) * NF + n0 + ncol;
        bdst = (uint32_t)k2 * BROWB + ncol * 4;          // byte offset in plane
    }

    const int lane = tid & 31, w = tid >> 5;
    const int wm = (w >> 2) * (BM / 2);                  // 2 warp rows
    const int wn = (w & 3) * (BN / 4);                   // 4 warp cols
    const int g  = lane >> 2, tg = lane & 3;

    float acc[MI][NI][4];
#pragma unroll
    for (int mi = 0; mi < MI; mi++)
#pragma unroll
        for (int ni = 0; ni < NI; ni++)
#pragma unroll
            for (int e = 0; e < 4; e++) acc[mi][ni][e] = 0.f;

    float4 aS[APT], bF0, bF1;

    // ---- prologue: stage chunk 0 into buffer 0 ----
#pragma unroll
    for (int i = 0; i < APT; i++) aS[i] = *(const float4*)(aptr[i]);
    if (bact) {
        bF0 = *(const float4*)(bptr0);
        bF1 = *(const float4*)(bptr0 + NF);
    }
#pragma unroll
    for (int i = 0; i < APT; i++) {
        uint2 hi, lo;
        split4(aS[i], hi, lo);
        *(uint2*)(sm + adst[i])       = hi;
        *(uint2*)(sm + adst[i] + APL) = lo;
    }
    if (bact) {
        uint4 hi, lo;
        packk4(bF0, bF1, hi, lo);
        *(uint4*)(sm + 2 * APL + bdst)        = hi;
        *(uint4*)(sm + 2 * APL + bdst + BPLP) = lo;
    }
    __syncthreads();

    for (int c = 0; c < NCH; c++) {
        // prefetch chunk c+1 (global latency overlaps the mma below)
        if (c + 1 < NCH) {
            const int k1 = (c + 1) * 16;
#pragma unroll
            for (int i = 0; i < APT; i++) aS[i] = *(const float4*)(aptr[i] + k1);
            if (bact) {
                const float* p = bptr0 + (size_t)k1 * NF;
                bF0 = *(const float4*)(p);
                bF1 = *(const float4*)(p + NF);
            }
        }

        const char* Ab = sm + (c & 1) * BUFSZ;
        const char* Bb = Ab + 2 * APL;

        // B fragments: single lds.32 per register from k-pair packed words
        uint32_t bh[NI][2], bl[NI][2];
#pragma unroll
        for (int ni = 0; ni < NI; ni++) {
            uint32_t w0 = (uint32_t)tg * BROWW + wn + ni * 8 + g;
            uint32_t w1 = w0 + 4 * BROWW;
            bh[ni][0] = *(const uint32_t*)(Bb + 4 * w0);
            bh[ni][1] = *(const uint32_t*)(Bb + 4 * w1);
            bl[ni][0] = *(const uint32_t*)(Bb + BPLP + 4 * w0);
            bl[ni][1] = *(const uint32_t*)(Bb + BPLP + 4 * w1);
        }

        // A fragments: hi plane first, MMA, then reuse the SAME regs for lo.
        uint32_t af[MI][4];
#pragma unroll
        for (int mi = 0; mi < MI; mi++) {
            uint32_t base = (uint32_t)(wm + mi * 16 + g) * ROWB + 4 * tg;
            af[mi][0] = *(const uint32_t*)(Ab + base);
            af[mi][1] = *(const uint32_t*)(Ab + base + 8 * ROWB);
            af[mi][2] = *(const uint32_t*)(Ab + base + 16);
            af[mi][3] = *(const uint32_t*)(Ab + base + 8 * ROWB + 16);
        }
#pragma unroll
        for (int mi = 0; mi < MI; mi++)
#pragma unroll
            for (int ni = 0; ni < NI; ni++) {
                MMA_BF16(acc[mi][ni], af[mi], bh[ni]);   // h*h
                MMA_BF16(acc[mi][ni], af[mi], bl[ni]);   // h*l
            }
#pragma unroll
        for (int mi = 0; mi < MI; mi++) {
            uint32_t base = (uint32_t)(wm + mi * 16 + g) * ROWB + 4 * tg + APL;
            af[mi][0] = *(const uint32_t*)(Ab + base);
            af[mi][1] = *(const uint32_t*)(Ab + base + 8 * ROWB);
            af[mi][2] = *(const uint32_t*)(Ab + base + 16);
            af[mi][3] = *(const uint32_t*)(Ab + base + 8 * ROWB + 16);
        }
#pragma unroll
        for (int mi = 0; mi < MI; mi++)
#pragma unroll
            for (int ni = 0; ni < NI; ni++)
                MMA_BF16(acc[mi][ni], af[mi], bh[ni]);   // l*h

        // store prefetched chunk into the other buffer
        if (c + 1 < NCH) {
            char* D = sm + ((c + 1) & 1) * BUFSZ;
#pragma unroll
            for (int i = 0; i < APT; i++) {
                uint2 hi, lo;
                split4(aS[i], hi, lo);
                *(uint2*)(D + adst[i])       = hi;
                *(uint2*)(D + adst[i] + APL) = lo;
            }
            if (bact) {
                uint4 hi, lo;
                packk4(bF0, bF1, hi, lo);
                *(uint4*)(D + 2 * APL + bdst)        = hi;
                *(uint4*)(D + 2 * APL + bdst + BPLP) = lo;
            }
        }
        __syncthreads();
    }

    // ----------------------------- epilogue (proven) -----------------------
    const float* bs = bias + (size_t)s * NF + n0;
    const float* gb = gbias + n0;
#pragma unroll
    for (int mi = 0; mi < MI; mi++) {
        const int rbase = wm + mi * 16 + g;
#pragma unroll
        for (int ni = 0; ni < NI; ni++) {
            const int c0 = wn + ni * 8 + 2 * tg;
            const float bv0 = bs[c0] + gb[c0];
            const float bv1 = bs[c0 + 1] + gb[c0 + 1];
#pragma unroll
            for (int half = 0; half < 2; half++) {
                const int r = rbase + half * 8;
                if (r < rows) {
                    float v0 = acc[mi][ni][half * 2 + 0] + bv0;
                    float v1 = acc[mi][ni][half * 2 + 1] + bv1;
                    if (RELU) { v0 = fmaxf(v0, 0.f); v1 = fmaxf(v1, 0.f); }
                    const int prow = off + m0 + r;
                    const int orow = (LAYER == 2) ? g_perm[prow] : prow;
                    *(float2*)(out + (size_t)orow * NF + n0 + c0) = make_float2(v0, v1);
                }
            }
        }
    }
}

// ---------------------------------------------------------------------------
extern "C" void kernel_launch(void* const* d_in, const int* in_sizes, int n_in,
                              void* d_out, int out_size) {
    const float* x     = (const float*)d_in[0];
    const int*   scene = (const int*)d_in[1];   // int32 or int64, auto-detected
    const float* W0  = (const float*)d_in[2];
    const float* b0  = (const float*)d_in[3];
    const float* gW0 = (const float*)d_in[4];
    const float* gb0 = (const float*)d_in[5];
    const float* W1  = (const float*)d_in[6];
    const float* b1  = (const float*)d_in[7];
    const float* gW1 = (const float*)d_in[8];
    const float* gb1 = (const float*)d_in[9];
    const float* W2  = (const float*)d_in[10];
    const float* b2  = (const float*)d_in[11];
    const float* gW2 = (const float*)d_in[12];
    const float* gb2 = (const float*)d_in[13];
    float* out = (float*)d_out;

    const int B = in_sizes[1];
    const int lt128 = (B + 127) / 128 + NS - 1;   // worst-case live tiles
    const int lt64  = (B + 63) / 64 + NS - 1;

    // smem: L0/L1: 2*(2*128*48 + 2*8*(128+8)*4) = 41984 (<48K, no opt-in)
    //       L2:    2*(2*64*48  + 2*8*(64+8)*4)  = 21504
    const int SM_L01 = 2 * (2 * 128 * 48 + 2 * 8 * (128 + 8) * 4);
    const int SM_L2  = 2 * (2 * 64 * 48 + 2 * 8 * (64 + 8) * 4);

    // launch order chosen so position #4 (ncu's observed capture slot) = gemm0
    k_scale_all<<<1024, 256>>>(W0, gW0, W1, gW1, W2, gW2);
    k_countscan<<<1, 256>>>(scene, B);
    k_scatter<<<(B + 255) / 256, 256>>>(scene, B);

    k_gemm<0, D0, D1, 128, 128, true ><<<dim3(lt128, D1 / 128), 256, SM_L01>>>(
        x, nullptr, b0, gb0, B);
    k_gemm<1, D1, D2, 128, 128, true ><<<dim3(lt128, D2 / 128), 256, SM_L01>>>(
        nullptr, nullptr, b1, gb1, B);
    k_gemm<2, D2, D3, 64, 64, false><<<dim3(lt64, 1), 256, SM_L2>>>(
        nullptr, out, b2, gb2, B);
}

// round 14
// speedup vs baseline: 1.0456x; 1.0456x over previous
#include <cuda_runtime.h>
#include <cuda_bf16.h>
#include <cstdint>

// ---------------------------------------------------------------------------
// STARDNN on GB300. R14 = R13 + K-chunk 16 -> 32 (half-staged prefetch, same
// peak staging registers as R12/R13). Halves barrier count per GEMM.
// Arithmetic order per accumulator unchanged -> rel_err must stay 8.738492e-06.
// ---------------------------------------------------------------------------

#define NS    7
#define MAXB  16384
#define D0    512
#define D1    512
#define D2    256
#define D3    64

// scratch (allocation-free: __device__ globals)
__device__ int   g_count[NS];
__device__ int   g_offset[NS];
__device__ int   g_cursor[NS];
__device__ int   g_tile128[NS + 1];
__device__ int   g_tile64[NS + 1];
__device__ int   g_perm[MAXB];
__device__ float g_h1[MAXB * D1];
__device__ float g_h2[MAXB * D2];
__device__ float g_SW0[NS * D0 * D1];
__device__ float g_SW1[NS * D1 * D2];
__device__ float g_SW2[NS * D2 * D3];

// ------------------------------ helpers ------------------------------------
#define MMA_BF16(d, a, b) \
    asm volatile("mma.sync.aligned.m16n8k16.row.col.f32.bf16.bf16.f32 " \
                 "{%0,%1,%2,%3}, {%4,%5,%6,%7}, {%8,%9}, {%0,%1,%2,%3};" \
                 : "+f"((d)[0]), "+f"((d)[1]), "+f"((d)[2]), "+f"((d)[3]) \
                 : "r"((a)[0]), "r"((a)[1]), "r"((a)[2]), "r"((a)[3]), \
                   "r"((b)[0]), "r"((b)[1]))

__device__ __forceinline__ void bsplit(float v, __nv_bfloat16& h, __nv_bfloat16& l) {
    h = __float2bfloat16(v);
    l = __float2bfloat16(v - __bfloat162float(h));
}

__device__ __forceinline__ uint32_t pack2(__nv_bfloat16 a, __nv_bfloat16 b) {
    union { __nv_bfloat16 h[2]; uint32_t u; } t;
    t.h[0] = a; t.h[1] = b;
    return t.u;
}

// split a float4 into hi/lo packed uint2 (k-adjacent pairs; for A staging)
__device__ __forceinline__ void split4(float4 v, uint2& hi, uint2& lo) {
    __nv_bfloat16 h0, l0, h1, l1, h2, l2, h3, l3;
    bsplit(v.x, h0, l0); bsplit(v.y, h1, l1);
    bsplit(v.z, h2, l2); bsplit(v.w, h3, l3);
    hi.x = pack2(h0, h1); hi.y = pack2(h2, h3);
    lo.x = pack2(l0, l1); lo.y = pack2(l2, l3);
}

// pack two k-adjacent rows (same 4 n's) into k-pair words (for B staging)
__device__ __forceinline__ void packk4(float4 f0, float4 f1, uint4& hi, uint4& lo) {
    __nv_bfloat16 ha, la, hb, lb;
    bsplit(f0.x, ha, la); bsplit(f1.x, hb, lb);
    hi.x = pack2(ha, hb); lo.x = pack2(la, lb);
    bsplit(f0.y, ha, la); bsplit(f1.y, hb, lb);
    hi.y = pack2(ha, hb); lo.y = pack2(la, lb);
    bsplit(f0.z, ha, la); bsplit(f1.z, hb, lb);
    hi.z = pack2(ha, hb); lo.z = pack2(la, lb);
    bsplit(f0.w, ha, la); bsplit(f1.w, hb, lb);
    hi.w = pack2(ha, hb); lo.w = pack2(la, lb);
}

// ------------------------------ bucketing ----------------------------------
__device__ __forceinline__ int scene_at(const int* __restrict__ p, int b, bool is64) {
    int v = is64 ? p[2 * b] : p[b];
    int s = v - 1;
    return (s < 0) ? 0 : (s >= NS ? NS - 1 : s);
}

__global__ __launch_bounds__(256) void k_countscan(const int* __restrict__ scene, int B) {
    __shared__ int hist[NS];
    if (threadIdx.x < NS) hist[threadIdx.x] = 0;
    __syncthreads();
    bool is64 = (scene[1] == 0);
    for (int b = threadIdx.x; b < B; b += 256)
        atomicAdd(&hist[scene_at(scene, b, is64)], 1);
    __syncthreads();
    if (threadIdx.x == 0) {
        int off = 0, t128 = 0, t64 = 0;
        for (int s = 0; s < NS; s++) {
            int c = hist[s];
            g_count[s] = c;
            g_offset[s] = off;
            g_cursor[s] = off;
            g_tile128[s] = t128;
            g_tile64[s] = t64;
            off += c;
            t128 += (c + 127) >> 7;
            t64  += (c + 63) >> 6;
        }
        g_tile128[NS] = t128;
        g_tile64[NS] = t64;
    }
}

__global__ void k_scatter(const int* __restrict__ scene, int B) {
    int b = blockIdx.x * blockDim.x + threadIdx.x;
    if (b < B) {
        bool is64 = (scene[1] == 0);
        int s = scene_at(scene, b, is64);
        int pos = atomicAdd(&g_cursor[s], 1);
        g_perm[pos] = b;
    }
}

__global__ void k_scale_all(const float* __restrict__ W0, const float* __restrict__ gW0,
                            const float* __restrict__ W1, const float* __restrict__ gW1,
                            const float* __restrict__ W2, const float* __restrict__ gW2) {
    int stride = gridDim.x * blockDim.x;
    int t = blockIdx.x * blockDim.x + threadIdx.x;
    for (int j = t; j < D0 * D1; j += stride) {
        float g = gW0[j];
#pragma unroll
        for (int s = 0; s < NS; s++) g_SW0[s * D0 * D1 + j] = W0[s * D0 * D1 + j] * g;
    }
    for (int j = t; j < D1 * D2; j += stride) {
        float g = gW1[j];
#pragma unroll
        for (int s = 0; s < NS; s++) g_SW1[s * D1 * D2 + j] = W1[s * D1 * D2 + j] * g;
    }
    for (int j = t; j < D2 * D3; j += stride) {
        float g = gW2[j];
#pragma unroll
        for (int s = 0; s < NS; s++) g_SW2[s * D2 * D3 + j] = W2[s * D2 * D3 + j] * g;
    }
}

// ------------------------------ mma GEMM -----------------------------------
// CTA: BM x BN tile. K in chunks of 32 (two k16 mma steps per barrier).
// A smem: [BM][32] bf16 rows, ROWB=80 (64B + 16B pad), hi/lo planes.
//   frag banks: 20g + tg (+8*ks/2... covered) -> conflict-free.
// B smem: 16 k-pair rows x (BN+8) words per plane; frag = single lds.32.
// Prefetch half-staged: A+B half0 -> mma ks=0 -> store half0 ->
//                       A+B half1 -> mma ks=16 -> store half1 -> barrier.
// Peak staging regs identical to R12 (16).
template <int LAYER, int K, int NF, int BM, int BN, bool RELU>
__global__ __launch_bounds__(256, 2) void k_gemm(const float* __restrict__ xin,
                                                 float* __restrict__ xout,
                                                 const float* __restrict__ bias,
                                                 const float* __restrict__ gbias,
                                                 int B) {
    constexpr int MI = BM / 2 / 16;
    constexpr int NI = BN / 4 / 8;
    constexpr int NCH = K / 32;
    constexpr int ROWB = 80;              // 32 bf16 (64B) + 16B pad
    constexpr int APL = BM * ROWB;
    constexpr int BROWW = BN + 8;
    constexpr int BROWB = BROWW * 4;
    constexpr int BPLP = 16 * BROWB;      // 16 k-pair rows per chunk
    constexpr int BUFSZ = 2 * APL + 2 * BPLP;
    constexpr int APT = BM / 64;          // A float4 loads per thread per half
    constexpr int BSLOTS = 8 * (BN / 4);  // B slots per half

    extern __shared__ char sm[];

    const int* tstart = (BM == 128) ? g_tile128 : g_tile64;
    const int t = blockIdx.x;
    if (t >= tstart[NS]) return;
    int s = 0;
    while (tstart[s + 1] <= t) s++;
    const int m0   = (t - tstart[s]) * BM;
    const int cnt  = g_count[s];
    const int off  = g_offset[s];
    const int rows = min(BM, cnt - m0);
    const int n0   = blockIdx.y * BN;
    const int tid  = threadIdx.x;

    const float* in = (LAYER == 0) ? xin : (LAYER == 1 ? g_h1 : g_h2);
    float*      out = (LAYER == 2) ? xout : (LAYER == 0 ? g_h1 : g_h2);
    const float* SW = (LAYER == 0) ? g_SW0 : (LAYER == 1 ? g_SW1 : g_SW2);

    // ---- A staging: APT float4 per thread per HALF (k-offset varies) ----
    const int aq = (tid & 3) * 4;                        // float col 0,4,8,12 in half
    const float* aptr[APT];
    uint32_t adst[APT];                                  // base byte off (half0)
#pragma unroll
    for (int i = 0; i < APT; i++) {
        int r = (tid >> 2) + i * 64;
        int pr = off + m0 + ((r < rows) ? r : 0);
        if (pr > B - 1) pr = B - 1;
        int grow = (LAYER == 0) ? g_perm[pr] : pr;
        aptr[i] = in + (size_t)grow * K + aq;
        adst[i] = (uint32_t)r * ROWB + aq * 2;
    }
    // ---- B staging: one (k-pair, n-quad) slot per active thread per half --
    const bool bact = (tid < BSLOTS);
    const float* bptr0 = nullptr;
    uint32_t bdst = 0;                                   // base byte off (half0)
    if (bact) {
        int k2 = tid / (BN / 4);                         // 0..7 within half
        int ncol = (tid % (BN / 4)) * 4;
        bptr0 = SW + ((size_t)s * K + 2 * k2) * NF + n0 + ncol;
        bdst = (uint32_t)k2 * BROWB + ncol * 4;
    }

    const int lane = tid & 31, w = tid >> 5;
    const int wm = (w >> 2) * (BM / 2);
    const int wn = (w & 3) * (BN / 4);
    const int g  = lane >> 2, tg = lane & 3;

    float acc[MI][NI][4];
#pragma unroll
    for (int mi = 0; mi < MI; mi++)
#pragma unroll
        for (int ni = 0; ni < NI; ni++)
#pragma unroll
            for (int e = 0; e < 4; e++) acc[mi][ni][e] = 0.f;

    float4 aS[APT], bF0, bF1;

    // ---- prologue: stage chunk 0 (both halves) into buffer 0 ----
#pragma unroll
    for (int h = 0; h < 2; h++) {
        const int kb = h * 16;
#pragma unroll
        for (int i = 0; i < APT; i++) aS[i] = *(const float4*)(aptr[i] + kb);
        if (bact) {
            bF0 = *(const float4*)(bptr0 + (size_t)kb * NF);
            bF1 = *(const float4*)(bptr0 + (size_t)(kb + 1) * NF);
        }
#pragma unroll
        for (int i = 0; i < APT; i++) {
            uint2 hi, lo;
            split4(aS[i], hi, lo);
            *(uint2*)(sm + adst[i] + h * 32)       = hi;
            *(uint2*)(sm + adst[i] + h * 32 + APL) = lo;
        }
        if (bact) {
            uint4 hi, lo;
            packk4(bF0, bF1, hi, lo);
            *(uint4*)(sm + 2 * APL + bdst + h * 8 * BROWB)        = hi;
            *(uint4*)(sm + 2 * APL + bdst + h * 8 * BROWB + BPLP) = lo;
        }
    }
    __syncthreads();

    for (int c = 0; c < NCH; c++) {
        const char* Ab = sm + (c & 1) * BUFSZ;
        const char* Bb = Ab + 2 * APL;
        char* Dst = sm + ((c + 1) & 1) * BUFSZ;
        const bool pf = (c + 1 < NCH);
        const int kc1 = (c + 1) * 32;

#pragma unroll
        for (int h = 0; h < 2; h++) {
            const int ks = h * 16;
            // prefetch half h of chunk c+1
            if (pf) {
                const int kb = kc1 + ks;
#pragma unroll
                for (int i = 0; i < APT; i++) aS[i] = *(const float4*)(aptr[i] + kb);
                if (bact) {
                    bF0 = *(const float4*)(bptr0 + (size_t)kb * NF);
                    bF1 = *(const float4*)(bptr0 + (size_t)(kb + 1) * NF);
                }
            }

            // B fragments for (c, ks): single lds.32 each
            uint32_t bh[NI][2], bl[NI][2];
#pragma unroll
            for (int ni = 0; ni < NI; ni++) {
                uint32_t w0 = (uint32_t)((ks >> 1) + tg) * BROWW + wn + ni * 8 + g;
                uint32_t w1 = w0 + 4 * BROWW;
                bh[ni][0] = *(const uint32_t*)(Bb + 4 * w0);
                bh[ni][1] = *(const uint32_t*)(Bb + 4 * w1);
                bl[ni][0] = *(const uint32_t*)(Bb + BPLP + 4 * w0);
                bl[ni][1] = *(const uint32_t*)(Bb + BPLP + 4 * w1);
            }
            // A fragments hi, MMA h*h + h*l, then reuse regs for lo, MMA l*h
            uint32_t af[MI][4];
#pragma unroll
            for (int mi = 0; mi < MI; mi++) {
                uint32_t base = (uint32_t)(wm + mi * 16 + g) * ROWB + ks * 2 + 4 * tg;
                af[mi][0] = *(const uint32_t*)(Ab + base);
                af[mi][1] = *(const uint32_t*)(Ab + base + 8 * ROWB);
                af[mi][2] = *(const uint32_t*)(Ab + base + 16);
                af[mi][3] = *(const uint32_t*)(Ab + base + 8 * ROWB + 16);
            }
#pragma unroll
            for (int mi = 0; mi < MI; mi++)
#pragma unroll
                for (int ni = 0; ni < NI; ni++) {
                    MMA_BF16(acc[mi][ni], af[mi], bh[ni]);   // h*h
                    MMA_BF16(acc[mi][ni], af[mi], bl[ni]);   // h*l
                }
#pragma unroll
            for (int mi = 0; mi < MI; mi++) {
                uint32_t base = (uint32_t)(wm + mi * 16 + g) * ROWB + ks * 2 + 4 * tg + APL;
                af[mi][0] = *(const uint32_t*)(Ab + base);
                af[mi][1] = *(const uint32_t*)(Ab + base + 8 * ROWB);
                af[mi][2] = *(const uint32_t*)(Ab + base + 16);
                af[mi][3] = *(const uint32_t*)(Ab + base + 8 * ROWB + 16);
            }
#pragma unroll
            for (int mi = 0; mi < MI; mi++)
#pragma unroll
                for (int ni = 0; ni < NI; ni++)
                    MMA_BF16(acc[mi][ni], af[mi], bh[ni]);   // l*h

            // store prefetched half h into the other buffer
            if (pf) {
#pragma unroll
                for (int i = 0; i < APT; i++) {
                    uint2 hi, lo;
                    split4(aS[i], hi, lo);
                    *(uint2*)(Dst + adst[i] + h * 32)       = hi;
                    *(uint2*)(Dst + adst[i] + h * 32 + APL) = lo;
                }
                if (bact) {
                    uint4 hi, lo;
                    packk4(bF0, bF1, hi, lo);
                    *(uint4*)(Dst + 2 * APL + bdst + h * 8 * BROWB)        = hi;
                    *(uint4*)(Dst + 2 * APL + bdst + h * 8 * BROWB + BPLP) = lo;
                }
            }
        }
        __syncthreads();
    }

    // ----------------------------- epilogue (proven) -----------------------
    const float* bs = bias + (size_t)s * NF + n0;
    const float* gb = gbias + n0;
#pragma unroll
    for (int mi = 0; mi < MI; mi++) {
        const int rbase = wm + mi * 16 + g;
#pragma unroll
        for (int ni = 0; ni < NI; ni++) {
            const int c0 = wn + ni * 8 + 2 * tg;
            const float bv0 = bs[c0] + gb[c0];
            const float bv1 = bs[c0 + 1] + gb[c0 + 1];
#pragma unroll
            for (int half = 0; half < 2; half++) {
                const int r = rbase + half * 8;
                if (r < rows) {
                    float v0 = acc[mi][ni][half * 2 + 0] + bv0;
                    float v1 = acc[mi][ni][half * 2 + 1] + bv1;
                    if (RELU) { v0 = fmaxf(v0, 0.f); v1 = fmaxf(v1, 0.f); }
                    const int prow = off + m0 + r;
                    const int orow = (LAYER == 2) ? g_perm[prow] : prow;
                    *(float2*)(out + (size_t)orow * NF + n0 + c0) = make_float2(v0, v1);
                }
            }
        }
    }
}

// ---------------------------------------------------------------------------
extern "C" void kernel_launch(void* const* d_in, const int* in_sizes, int n_in,
                              void* d_out, int out_size) {
    const float* x     = (const float*)d_in[0];
    const int*   scene = (const int*)d_in[1];   // int32 or int64, auto-detected
    const float* W0  = (const float*)d_in[2];
    const float* b0  = (const float*)d_in[3];
    const float* gW0 = (const float*)d_in[4];
    const float* gb0 = (const float*)d_in[5];
    const float* W1  = (const float*)d_in[6];
    const float* b1  = (const float*)d_in[7];
    const float* gW1 = (const float*)d_in[8];
    const float* gb1 = (const float*)d_in[9];
    const float* W2  = (const float*)d_in[10];
    const float* b2  = (const float*)d_in[11];
    const float* gW2 = (const float*)d_in[12];
    const float* gb2 = (const float*)d_in[13];
    float* out = (float*)d_out;

    const int B = in_sizes[1];
    const int lt128 = (B + 127) / 128 + NS - 1;
    const int lt64  = (B + 63) / 64 + NS - 1;

    // smem: L0/L1: 2*(2*128*80 + 2*16*(128+8)*4) = 75776 (needs opt-in)
    //       L2:    2*(2*64*80  + 2*16*(64+8)*4)  = 38912 (under 48K)
    const int SM_L01 = 2 * (2 * 128 * 80 + 2 * 16 * (128 + 8) * 4);
    const int SM_L2  = 2 * (2 * 64 * 80 + 2 * 16 * (64 + 8) * 4);

    cudaFuncSetAttribute(k_gemm<0, D0, D1, 128, 128, true >,
                         cudaFuncAttributeMaxDynamicSharedMemorySize, SM_L01);
    cudaFuncSetAttribute(k_gemm<1, D1, D2, 128, 128, true >,
                         cudaFuncAttributeMaxDynamicSharedMemorySize, SM_L01);

    k_scale_all<<<1024, 256>>>(W0, gW0, W1, gW1, W2, gW2);
    k_countscan<<<1, 256>>>(scene, B);
    k_scatter<<<(B + 255) / 256, 256>>>(scene, B);

    k_gemm<0, D0, D1, 128, 128, true ><<<dim3(lt128, D1 / 128), 256, SM_L01>>>(
        x, nullptr, b0, gb0, B);
    k_gemm<1, D1, D2, 128, 128, true ><<<dim3(lt128, D2 / 128), 256, SM_L01>>>(
        nullptr, nullptr, b1, gb1, B);
    k_gemm<2, D2, D3, 64, 64, false><<<dim3(lt64, 1), 256, SM_L2>>>(
        nullptr, out, b2, gb2, B);
}

// round 15
// speedup vs baseline: 1.3367x; 1.2784x over previous
#include <cuda_runtime.h>
#include <cuda_fp16.h>
#include <cstdint>

// ---------------------------------------------------------------------------
// STARDNN on GB300. R15 = R14 structure with fp16x2 numerics:
//   A (activations) rounded to single fp16; B (weights) split fp16 hi/lo.
//   D += A*Bh + A*Bl   (2 MMAs per acc instead of 3; A smem 1 plane)
// Error model: dominant term = fp16 rounding of A (2^-12) -> rel_err ~1.4e-4
// (calibrated against bf16x3's measured 8.74e-6 for 2^-16 dropped terms).
// Everything else (tiles, prefetch, barriers, scaffolding) R14-identical.
// ---------------------------------------------------------------------------

#define NS    7
#define MAXB  16384
#define D0    512
#define D1    512
#define D2    256
#define D3    64

// scratch (allocation-free: __device__ globals)
__device__ int   g_count[NS];
__device__ int   g_offset[NS];
__device__ int   g_cursor[NS];
__device__ int   g_tile128[NS + 1];
__device__ int   g_tile64[NS + 1];
__device__ int   g_perm[MAXB];
__device__ float g_h1[MAXB * D1];
__device__ float g_h2[MAXB * D2];
__device__ float g_SW0[NS * D0 * D1];
__device__ float g_SW1[NS * D1 * D2];
__device__ float g_SW2[NS * D2 * D3];

// ------------------------------ helpers ------------------------------------
#define MMA_FP16(d, a, b) \
    asm volatile("mma.sync.aligned.m16n8k16.row.col.f32.f16.f16.f32 " \
                 "{%0,%1,%2,%3}, {%4,%5,%6,%7}, {%8,%9}, {%0,%1,%2,%3};" \
                 : "+f"((d)[0]), "+f"((d)[1]), "+f"((d)[2]), "+f"((d)[3]) \
                 : "r"((a)[0]), "r"((a)[1]), "r"((a)[2]), "r"((a)[3]), \
                   "r"((b)[0]), "r"((b)[1]))

__device__ __forceinline__ uint32_t pack2h(__half a, __half b) {
    union { __half h[2]; uint32_t u; } t;
    t.h[0] = a; t.h[1] = b;
    return t.u;
}

// A staging: float4 (4 k-adjacent fp32) -> 4 fp16 packed into uint2
__device__ __forceinline__ void cvt4h(float4 v, uint2& o) {
    o.x = pack2h(__float2half_rn(v.x), __float2half_rn(v.y));
    o.y = pack2h(__float2half_rn(v.z), __float2half_rn(v.w));
}

// B staging: rows k (f0) and k+1 (f1), 4 n's -> k-pair words, fp16 hi/lo split
__device__ __forceinline__ void packk4h(float4 f0, float4 f1, uint4& hi, uint4& lo) {
    __half ha, hb;
    ha = __float2half_rn(f0.x); hb = __float2half_rn(f1.x);
    hi.x = pack2h(ha, hb);
    lo.x = pack2h(__float2half_rn(f0.x - __half2float(ha)),
                  __float2half_rn(f1.x - __half2float(hb)));
    ha = __float2half_rn(f0.y); hb = __float2half_rn(f1.y);
    hi.y = pack2h(ha, hb);
    lo.y = pack2h(__float2half_rn(f0.y - __half2float(ha)),
                  __float2half_rn(f1.y - __half2float(hb)));
    ha = __float2half_rn(f0.z); hb = __float2half_rn(f1.z);
    hi.z = pack2h(ha, hb);
    lo.z = pack2h(__float2half_rn(f0.z - __half2float(ha)),
                  __float2half_rn(f1.z - __half2float(hb)));
    ha = __float2half_rn(f0.w); hb = __float2half_rn(f1.w);
    hi.w = pack2h(ha, hb);
    lo.w = pack2h(__float2half_rn(f0.w - __half2float(ha)),
                  __float2half_rn(f1.w - __half2float(hb)));
}

// ------------------------------ bucketing ----------------------------------
__device__ __forceinline__ int scene_at(const int* __restrict__ p, int b, bool is64) {
    int v = is64 ? p[2 * b] : p[b];
    int s = v - 1;
    return (s < 0) ? 0 : (s >= NS ? NS - 1 : s);
}

__global__ __launch_bounds__(256) void k_countscan(const int* __restrict__ scene, int B) {
    __shared__ int hist[NS];
    if (threadIdx.x < NS) hist[threadIdx.x] = 0;
    __syncthreads();
    bool is64 = (scene[1] == 0);
    for (int b = threadIdx.x; b < B; b += 256)
        atomicAdd(&hist[scene_at(scene, b, is64)], 1);
    __syncthreads();
    if (threadIdx.x == 0) {
        int off = 0, t128 = 0, t64 = 0;
        for (int s = 0; s < NS; s++) {
            int c = hist[s];
            g_count[s] = c;
            g_offset[s] = off;
            g_cursor[s] = off;
            g_tile128[s] = t128;
            g_tile64[s] = t64;
            off += c;
            t128 += (c + 127) >> 7;
            t64  += (c + 63) >> 6;
        }
        g_tile128[NS] = t128;
        g_tile64[NS] = t64;
    }
}

__global__ void k_scatter(const int* __restrict__ scene, int B) {
    int b = blockIdx.x * blockDim.x + threadIdx.x;
    if (b < B) {
        bool is64 = (scene[1] == 0);
        int s = scene_at(scene, b, is64);
        int pos = atomicAdd(&g_cursor[s], 1);
        g_perm[pos] = b;
    }
}

__global__ void k_scale_all(const float* __restrict__ W0, const float* __restrict__ gW0,
                            const float* __restrict__ W1, const float* __restrict__ gW1,
                            const float* __restrict__ W2, const float* __restrict__ gW2) {
    int stride = gridDim.x * blockDim.x;
    int t = blockIdx.x * blockDim.x + threadIdx.x;
    for (int j = t; j < D0 * D1; j += stride) {
        float g = gW0[j];
#pragma unroll
        for (int s = 0; s < NS; s++) g_SW0[s * D0 * D1 + j] = W0[s * D0 * D1 + j] * g;
    }
    for (int j = t; j < D1 * D2; j += stride) {
        float g = gW1[j];
#pragma unroll
        for (int s = 0; s < NS; s++) g_SW1[s * D1 * D2 + j] = W1[s * D1 * D2 + j] * g;
    }
    for (int j = t; j < D2 * D3; j += stride) {
        float g = gW2[j];
#pragma unroll
        for (int s = 0; s < NS; s++) g_SW2[s * D2 * D3 + j] = W2[s * D2 * D3 + j] * g;
    }
}

// ------------------------------ mma GEMM -----------------------------------
// CTA: BM x BN tile. K in chunks of 32 (two k16 steps per barrier).
// A smem: single fp16 plane [BM][32] rows, ROWB=80 (64B + 16B pad).
// B smem: fp16 hi/lo planes, 16 k-pair rows x (BN+8) words each.
// Per k16 step/thread: 16 A lds.32 + 16 B lds.32 + 32 MMA (A*Bh, A*Bl).
template <int LAYER, int K, int NF, int BM, int BN, bool RELU>
__global__ __launch_bounds__(256, 2) void k_gemm(const float* __restrict__ xin,
                                                 float* __restrict__ xout,
                                                 const float* __restrict__ bias,
                                                 const float* __restrict__ gbias,
                                                 int B) {
    constexpr int MI = BM / 2 / 16;
    constexpr int NI = BN / 4 / 8;
    constexpr int NCH = K / 32;
    constexpr int ROWB = 80;              // 32 fp16 (64B) + 16B pad
    constexpr int APL = BM * ROWB;        // single A plane
    constexpr int BROWW = BN + 8;
    constexpr int BROWB = BROWW * 4;
    constexpr int BPLP = 16 * BROWB;      // one B plane (16 k-pair rows)
    constexpr int BUFSZ = APL + 2 * BPLP;
    constexpr int APT = BM / 64;          // A float4 loads per thread per half
    constexpr int BSLOTS = 8 * (BN / 4);  // B slots per half

    extern __shared__ char sm[];

    const int* tstart = (BM == 128) ? g_tile128 : g_tile64;
    const int t = blockIdx.x;
    if (t >= tstart[NS]) return;
    int s = 0;
    while (tstart[s + 1] <= t) s++;
    const int m0   = (t - tstart[s]) * BM;
    const int cnt  = g_count[s];
    const int off  = g_offset[s];
    const int rows = min(BM, cnt - m0);
    const int n0   = blockIdx.y * BN;
    const int tid  = threadIdx.x;

    const float* in = (LAYER == 0) ? xin : (LAYER == 1 ? g_h1 : g_h2);
    float*      out = (LAYER == 2) ? xout : (LAYER == 0 ? g_h1 : g_h2);
    const float* SW = (LAYER == 0) ? g_SW0 : (LAYER == 1 ? g_SW1 : g_SW2);

    // ---- A staging: APT float4 per thread per HALF ----
    const int aq = (tid & 3) * 4;                        // float col 0,4,8,12 in half
    const float* aptr[APT];
    uint32_t adst[APT];
#pragma unroll
    for (int i = 0; i < APT; i++) {
        int r = (tid >> 2) + i * 64;
        int pr = off + m0 + ((r < rows) ? r : 0);
        if (pr > B - 1) pr = B - 1;
        int grow = (LAYER == 0) ? g_perm[pr] : pr;
        aptr[i] = in + (size_t)grow * K + aq;
        adst[i] = (uint32_t)r * ROWB + aq * 2;
    }
    // ---- B staging: one (k-pair, n-quad) slot per active thread per half --
    const bool bact = (tid < BSLOTS);
    const float* bptr0 = nullptr;
    uint32_t bdst = 0;
    if (bact) {
        int k2 = tid / (BN / 4);                         // 0..7 within half
        int ncol = (tid % (BN / 4)) * 4;
        bptr0 = SW + ((size_t)s * K + 2 * k2) * NF + n0 + ncol;
        bdst = (uint32_t)k2 * BROWB + ncol * 4;
    }

    const int lane = tid & 31, w = tid >> 5;
    const int wm = (w >> 2) * (BM / 2);
    const int wn = (w & 3) * (BN / 4);
    const int g  = lane >> 2, tg = lane & 3;

    float acc[MI][NI][4];
#pragma unroll
    for (int mi = 0; mi < MI; mi++)
#pragma unroll
        for (int ni = 0; ni < NI; ni++)
#pragma unroll
            for (int e = 0; e < 4; e++) acc[mi][ni][e] = 0.f;

    float4 aS[APT], bF0, bF1;

    // ---- prologue: stage chunk 0 (both halves) into buffer 0 ----
#pragma unroll
    for (int h = 0; h < 2; h++) {
        const int kb = h * 16;
#pragma unroll
        for (int i = 0; i < APT; i++) aS[i] = *(const float4*)(aptr[i] + kb);
        if (bact) {
            bF0 = *(const float4*)(bptr0 + (size_t)kb * NF);
            bF1 = *(const float4*)(bptr0 + (size_t)(kb + 1) * NF);
        }
#pragma unroll
        for (int i = 0; i < APT; i++) {
            uint2 av;
            cvt4h(aS[i], av);
            *(uint2*)(sm + adst[i] + h * 32) = av;
        }
        if (bact) {
            uint4 hi, lo;
            packk4h(bF0, bF1, hi, lo);
            *(uint4*)(sm + APL + bdst + h * 8 * BROWB)        = hi;
            *(uint4*)(sm + APL + bdst + h * 8 * BROWB + BPLP) = lo;
        }
    }
    __syncthreads();

    for (int c = 0; c < NCH; c++) {
        const char* Ab = sm + (c & 1) * BUFSZ;
        const char* Bb = Ab + APL;
        char* Dst = sm + ((c + 1) & 1) * BUFSZ;
        const bool pf = (c + 1 < NCH);
        const int kc1 = (c + 1) * 32;

#pragma unroll
        for (int h = 0; h < 2; h++) {
            const int ks = h * 16;
            // prefetch half h of chunk c+1
            if (pf) {
                const int kb = kc1 + ks;
#pragma unroll
                for (int i = 0; i < APT; i++) aS[i] = *(const float4*)(aptr[i] + kb);
                if (bact) {
                    bF0 = *(const float4*)(bptr0 + (size_t)kb * NF);
                    bF1 = *(const float4*)(bptr0 + (size_t)(kb + 1) * NF);
                }
            }

            // B fragments (hi + lo planes): single lds.32 each
            uint32_t bh[NI][2], bl[NI][2];
#pragma unroll
            for (int ni = 0; ni < NI; ni++) {
                uint32_t w0 = (uint32_t)((ks >> 1) + tg) * BROWW + wn + ni * 8 + g;
                uint32_t w1 = w0 + 4 * BROWW;
                bh[ni][0] = *(const uint32_t*)(Bb + 4 * w0);
                bh[ni][1] = *(const uint32_t*)(Bb + 4 * w1);
                bl[ni][0] = *(const uint32_t*)(Bb + BPLP + 4 * w0);
                bl[ni][1] = *(const uint32_t*)(Bb + BPLP + 4 * w1);
            }
            // A fragments (single plane)
            uint32_t af[MI][4];
#pragma unroll
            for (int mi = 0; mi < MI; mi++) {
                uint32_t base = (uint32_t)(wm + mi * 16 + g) * ROWB + ks * 2 + 4 * tg;
                af[mi][0] = *(const uint32_t*)(Ab + base);
                af[mi][1] = *(const uint32_t*)(Ab + base + 8 * ROWB);
                af[mi][2] = *(const uint32_t*)(Ab + base + 16);
                af[mi][3] = *(const uint32_t*)(Ab + base + 8 * ROWB + 16);
            }
#pragma unroll
            for (int mi = 0; mi < MI; mi++)
#pragma unroll
                for (int ni = 0; ni < NI; ni++) {
                    MMA_FP16(acc[mi][ni], af[mi], bh[ni]);   // A*Bh
                    MMA_FP16(acc[mi][ni], af[mi], bl[ni]);   // A*Bl
                }

            // store prefetched half h into the other buffer
            if (pf) {
#pragma unroll
                for (int i = 0; i < APT; i++) {
                    uint2 av;
                    cvt4h(aS[i], av);
                    *(uint2*)(Dst + adst[i] + h * 32) = av;
                }
                if (bact) {
                    uint4 hi, lo;
                    packk4h(bF0, bF1, hi, lo);
                    *(uint4*)(Dst + APL + bdst + h * 8 * BROWB)        = hi;
                    *(uint4*)(Dst + APL + bdst + h * 8 * BROWB + BPLP) = lo;
                }
            }
        }
        __syncthreads();
    }

    // ----------------------------- epilogue (proven) -----------------------
    const float* bs = bias + (size_t)s * NF + n0;
    const float* gb = gbias + n0;
#pragma unroll
    for (int mi = 0; mi < MI; mi++) {
        const int rbase = wm + mi * 16 + g;
#pragma unroll
        for (int ni = 0; ni < NI; ni++) {
            const int c0 = wn + ni * 8 + 2 * tg;
            const float bv0 = bs[c0] + gb[c0];
            const float bv1 = bs[c0 + 1] + gb[c0 + 1];
#pragma unroll
            for (int half = 0; half < 2; half++) {
                const int r = rbase + half * 8;
                if (r < rows) {
                    float v0 = acc[mi][ni][half * 2 + 0] + bv0;
                    float v1 = acc[mi][ni][half * 2 + 1] + bv1;
                    if (RELU) { v0 = fmaxf(v0, 0.f); v1 = fmaxf(v1, 0.f); }
                    const int prow = off + m0 + r;
                    const int orow = (LAYER == 2) ? g_perm[prow] : prow;
                    *(float2*)(out + (size_t)orow * NF + n0 + c0) = make_float2(v0, v1);
                }
            }
        }
    }
}

// ---------------------------------------------------------------------------
extern "C" void kernel_launch(void* const* d_in, const int* in_sizes, int n_in,
                              void* d_out, int out_size) {
    const float* x     = (const float*)d_in[0];
    const int*   scene = (const int*)d_in[1];   // int32 or int64, auto-detected
    const float* W0  = (const float*)d_in[2];
    const float* b0  = (const float*)d_in[3];
    const float* gW0 = (const float*)d_in[4];
    const float* gb0 = (const float*)d_in[5];
    const float* W1  = (const float*)d_in[6];
    const float* b1  = (const float*)d_in[7];
    const float* gW1 = (const float*)d_in[8];
    const float* gb1 = (const float*)d_in[9];
    const float* W2  = (const float*)d_in[10];
    const float* b2  = (const float*)d_in[11];
    const float* gW2 = (const float*)d_in[12];
    const float* gb2 = (const float*)d_in[13];
    float* out = (float*)d_out;

    const int B = in_sizes[1];
    const int lt128 = (B + 127) / 128 + NS - 1;
    const int lt64  = (B + 63) / 64 + NS - 1;

    // smem: L0/L1: 2*(128*80 + 2*16*(128+8)*4) = 55296 (opt-in; proven in R14)
    //       L2:    2*(64*80  + 2*16*(64+8)*4)  = 28672 (< 48K)
    const int SM_L01 = 2 * (128 * 80 + 2 * 16 * (128 + 8) * 4);
    const int SM_L2  = 2 * (64 * 80 + 2 * 16 * (64 + 8) * 4);

    cudaFuncSetAttribute(k_gemm<0, D0, D1, 128, 128, true >,
                         cudaFuncAttributeMaxDynamicSharedMemorySize, SM_L01);
    cudaFuncSetAttribute(k_gemm<1, D1, D2, 128, 128, true >,
                         cudaFuncAttributeMaxDynamicSharedMemorySize, SM_L01);

    k_scale_all<<<1024, 256>>>(W0, gW0, W1, gW1, W2, gW2);
    k_countscan<<<1, 256>>>(scene, B);
    k_scatter<<<(B + 255) / 256, 256>>>(scene, B);

    k_gemm<0, D0, D1, 128, 128, true ><<<dim3(lt128, D1 / 128), 256, SM_L01>>>(
        x, nullptr, b0, gb0, B);
    k_gemm<1, D1, D2, 128, 128, true ><<<dim3(lt128, D2 / 128), 256, SM_L01>>>(
        nullptr, nullptr, b1, gb1, B);
    k_gemm<2, D2, D3, 64, 64, false><<<dim3(lt64, 1), 256, SM_L2>>>(
        nullptr, out, b2, gb2, B);
}

// round 16
// speedup vs baseline: 1.5032x; 1.1245x over previous
#include <cuda_runtime.h>
#include <cuda_fp16.h>
#include <cstdint>

// ---------------------------------------------------------------------------
// STARDNN on GB300. R16: fp16x2 (proven R15 numerics, bit-identical) with a
// cp.async 4-deep pipeline. All conversions hoisted out of the GEMMs:
//   - weights pre-split fp16 hi/lo k-pair words in gmem (k_splitw)
//   - x gathered+converted to fp16 once (k_xcvt)
//   - epilogues write next layer's activations as fp16 directly
// All __device__ globals referenced ONLY inside device code (the R8/R9
// host-side-symbol-argument pattern is the quarantined bug).
// ---------------------------------------------------------------------------

#define NS    7
#define MAXB  16384
#define D0    512
#define D1    512
#define D2    256
#define D3    64

// ------------------------- device scratch (no allocs) ----------------------
__device__ int g_count[NS];
__device__ int g_offset[NS];
__device__ int g_cursor[NS];
__device__ int g_tile128[NS + 1];
__device__ int g_tile64[NS + 1];
__device__ int g_perm[MAXB];
// activations fp16, permuted row order
__device__ __align__(256) __half g_ax[MAXB * D0];
__device__ __align__(256) __half g_a1[MAXB * D1];
__device__ __align__(256) __half g_a2[MAXB * D2];
// weights fp16 hi/lo, k-pair packed words [s][K/2][N]
__device__ __align__(256) uint32_t g_Bh0[NS * (D0 / 2) * D1], g_Bl0[NS * (D0 / 2) * D1];
__device__ __align__(256) uint32_t g_Bh1[NS * (D1 / 2) * D2], g_Bl1[NS * (D1 / 2) * D2];
__device__ __align__(256) uint32_t g_Bh2[NS * (D2 / 2) * D3], g_Bl2[NS * (D2 / 2) * D3];

// ------------------------------ helpers ------------------------------------
__device__ __forceinline__ uint32_t smem_u32(const void* p) {
    uint32_t a;
    asm("{ .reg .u64 t; cvta.to.shared.u64 t, %1; cvt.u32.u64 %0, t; }" : "=r"(a) : "l"(p));
    return a;
}

#define CP16(dst, src) \
    asm volatile("cp.async.cg.shared.global [%0], [%1], 16;" :: "r"(dst), "l"(src))
#define CP_COMMIT() asm volatile("cp.async.commit_group;" ::: "memory")
#define CP_WAIT2()  asm volatile("cp.async.wait_group 2;" ::: "memory")

#define MMA_FP16(d, a, b) \
    asm volatile("mma.sync.aligned.m16n8k16.row.col.f32.f16.f16.f32 " \
                 "{%0,%1,%2,%3}, {%4,%5,%6,%7}, {%8,%9}, {%0,%1,%2,%3};" \
                 : "+f"((d)[0]), "+f"((d)[1]), "+f"((d)[2]), "+f"((d)[3]) \
                 : "r"((a)[0]), "r"((a)[1]), "r"((a)[2]), "r"((a)[3]), \
                   "r"((b)[0]), "r"((b)[1]))

__device__ __forceinline__ uint32_t pack2h(__half a, __half b) {
    union { __half h[2]; uint32_t u; } t;
    t.h[0] = a; t.h[1] = b;
    return t.u;
}

// ------------------------------ bucketing (proven) -------------------------
__device__ __forceinline__ int scene_at(const int* __restrict__ p, int b, bool is64) {
    int v = is64 ? p[2 * b] : p[b];
    int s = v - 1;
    return (s < 0) ? 0 : (s >= NS ? NS - 1 : s);
}

__global__ __launch_bounds__(256) void k_countscan(const int* __restrict__ scene, int B) {
    __shared__ int hist[NS];
    if (threadIdx.x < NS) hist[threadIdx.x] = 0;
    __syncthreads();
    bool is64 = (scene[1] == 0);
    for (int b = threadIdx.x; b < B; b += 256)
        atomicAdd(&hist[scene_at(scene, b, is64)], 1);
    __syncthreads();
    if (threadIdx.x == 0) {
        int off = 0, t128 = 0, t64 = 0;
        for (int s = 0; s < NS; s++) {
            int c = hist[s];
            g_count[s] = c;
            g_offset[s] = off;
            g_cursor[s] = off;
            g_tile128[s] = t128;
            g_tile64[s] = t64;
            off += c;
            t128 += (c + 127) >> 7;
            t64  += (c + 63) >> 6;
        }
        g_tile128[NS] = t128;
        g_tile64[NS] = t64;
    }
}

__global__ void k_scatter(const int* __restrict__ scene, int B) {
    int b = blockIdx.x * blockDim.x + threadIdx.x;
    if (b < B) {
        bool is64 = (scene[1] == 0);
        int s = scene_at(scene, b, is64);
        int pos = atomicAdd(&g_cursor[s], 1);
        g_perm[pos] = b;
    }
}

// gather x via perm, convert to fp16 (same rn conversion as R15 staging)
__global__ __launch_bounds__(256) void k_xcvt(const float* __restrict__ x, int B) {
    int i = blockIdx.x * blockDim.x + threadIdx.x;
    int total = B * (D0 / 8);
    if (i >= total) return;
    int p = i / (D0 / 8), j = (i % (D0 / 8)) * 8;
    int src = g_perm[p];
    const float4* sp = (const float4*)(x + (size_t)src * D0 + j);
    float4 v0 = sp[0], v1 = sp[1];
    uint4 o;
    o.x = pack2h(__float2half_rn(v0.x), __float2half_rn(v0.y));
    o.y = pack2h(__float2half_rn(v0.z), __float2half_rn(v0.w));
    o.z = pack2h(__float2half_rn(v1.x), __float2half_rn(v1.y));
    o.w = pack2h(__float2half_rn(v1.z), __float2half_rn(v1.w));
    *(uint4*)(g_ax + (size_t)p * D0 + j) = o;
}

// weight prep: scale by gW, fp16 hi/lo split, k-pair packed words [s][K/2][N]
__device__ void splitw_sec(const float* __restrict__ W, const float* __restrict__ gW,
                           uint32_t* __restrict__ dh, uint32_t* __restrict__ dl,
                           int KD, int ND, int t, int stride) {
    const int TOT = (KD / 2) * ND;
    for (int j = t; j < TOT; j += stride) {
        int k2 = j / ND, n = j % ND;
        size_t i0 = (size_t)(2 * k2) * ND + n;
        size_t i1 = i0 + ND;
        float ga = gW[i0], gb = gW[i1];
        for (int s = 0; s < NS; s++) {
            size_t wb = (size_t)s * KD * ND;
            float w0 = W[wb + i0] * ga;
            float w1 = W[wb + i1] * gb;
            __half h0 = __float2half_rn(w0), h1 = __float2half_rn(w1);
            dh[(size_t)s * TOT + j] = pack2h(h0, h1);
            dl[(size_t)s * TOT + j] = pack2h(__float2half_rn(w0 - __half2float(h0)),
                                             __float2half_rn(w1 - __half2float(h1)));
        }
    }
}

__global__ __launch_bounds__(256) void k_splitw(
    const float* __restrict__ W0, const float* __restrict__ gW0,
    const float* __restrict__ W1, const float* __restrict__ gW1,
    const float* __restrict__ W2, const float* __restrict__ gW2) {
    int t = blockIdx.x * blockDim.x + threadIdx.x;
    int stride = gridDim.x * blockDim.x;
    splitw_sec(W0, gW0, g_Bh0, g_Bl0, D0, D1, t, stride);
    splitw_sec(W1, gW1, g_Bh1, g_Bl1, D1, D2, t, stride);
    splitw_sec(W2, gW2, g_Bh2, g_Bl2, D2, D3, t, stride);
}

// ------------------------------ mma GEMM -----------------------------------
// CTA: BM x BN tile. K in chunks of 32; 4-deep cp.async pipeline (depth 3 in
// flight).  A smem: fp16 [BM][32] rows, ROWB=80.  B smem: fp16 hi/lo k-pair
// planes, 16 rows x (BN+8) words.  Frag mappings identical to R15 (proven).
template <int LAYER, int K, int NF, int BM, int BN, bool RELU>
__global__ __launch_bounds__(256, 2) void k_gemm(float* __restrict__ fout,
                                                 const float* __restrict__ bias,
                                                 const float* __restrict__ gbias,
                                                 int B) {
    constexpr int MI = BM / 2 / 16;
    constexpr int NI = BN / 4 / 8;
    constexpr int NCH = K / 32;
    constexpr int ROWB = 80;
    constexpr int APL = BM * ROWB;
    constexpr int BROWW = BN + 8;
    constexpr int BROWB = BROWW * 4;
    constexpr int BPLP = 16 * BROWB;
    constexpr int BUFSZ = APL + 2 * BPLP;
    constexpr int APT4 = BM * 4 / 256;        // A 16B chunks per thread
    constexpr int BCH  = 2 * 16 * (BN / 4);   // B 16B chunks (both planes)
    constexpr int BPT4 = BCH / 256;

    extern __shared__ char smc[];
    const uint32_t sb = smem_u32(smc);

    const int* tstart = (BM == 128) ? g_tile128 : g_tile64;
    const int t = blockIdx.x;
    if (t >= tstart[NS]) return;
    int s = 0;
    while (tstart[s + 1] <= t) s++;
    const int m0   = (t - tstart[s]) * BM;
    const int cnt  = g_count[s];
    const int off  = g_offset[s];
    const int rows = min(BM, cnt - m0);
    const int n0   = blockIdx.y * BN;
    const int tid  = threadIdx.x;

    const __half* Ain = (LAYER == 0) ? g_ax : (LAYER == 1 ? g_a1 : g_a2);
    const uint32_t* Bh = (LAYER == 0) ? g_Bh0 : (LAYER == 1 ? g_Bh1 : g_Bh2);
    const uint32_t* Bl = (LAYER == 0) ? g_Bl0 : (LAYER == 1 ? g_Bl1 : g_Bl2);
    __half* Aout = (LAYER == 0) ? g_a1 : g_a2;

    // ---- cp.async descriptors (chunk-invariant; only k advances) ----
    const char* asrc[APT4];
    uint32_t adst[APT4];
#pragma unroll
    for (int i = 0; i < APT4; i++) {
        int idx = tid + i * 256;
        int row = idx >> 2, q = idx & 3;
        int pr = off + m0 + ((row < rows) ? row : 0);
        if (pr > B - 1) pr = B - 1;
        asrc[i] = (const char*)(Ain + (size_t)pr * K) + q * 16;
        adst[i] = sb + (uint32_t)row * ROWB + q * 16;
    }
    const char* bsrc[BPT4];
    uint32_t bdst[BPT4];
#pragma unroll
    for (int i = 0; i < BPT4; i++) {
        int idx = tid + i * 256;
        int plane = idx / (BCH / 2);
        int rem = idx % (BCH / 2);
        int krow = rem / (BN / 4), q = rem % (BN / 4);
        const uint32_t* P = plane ? Bl : Bh;
        bsrc[i] = (const char*)(P + (size_t)s * (K / 2) * NF + (size_t)krow * NF + n0 + q * 4);
        bdst[i] = sb + APL + (uint32_t)plane * BPLP + (uint32_t)krow * BROWB + q * 16;
    }

    const int lane = tid & 31, w = tid >> 5;
    const int wm = (w >> 2) * (BM / 2);
    const int wn = (w & 3) * (BN / 4);
    const int g  = lane >> 2, tg = lane & 3;

    float acc[MI][NI][4];
#pragma unroll
    for (int mi = 0; mi < MI; mi++)
#pragma unroll
        for (int ni = 0; ni < NI; ni++)
#pragma unroll
            for (int e = 0; e < 4; e++) acc[mi][ni][e] = 0.f;

    // ---- prologue: issue chunks 0..2 ----
#pragma unroll
    for (int p = 0; p < 3; p++) {
        if (p < NCH) {
            const uint32_t bo = (uint32_t)p * BUFSZ;
#pragma unroll
            for (int i = 0; i < APT4; i++) CP16(adst[i] + bo, asrc[i] + (size_t)p * 64);
#pragma unroll
            for (int i = 0; i < BPT4; i++) CP16(bdst[i] + bo, bsrc[i] + (size_t)p * 64 * NF);
        }
        CP_COMMIT();
    }

    for (int c = 0; c < NCH; c++) {
        CP_WAIT2();
        __syncthreads();

        // issue chunk c+3 into buffer (c+3)&3 (freed by the barrier above)
        if (c + 3 < NCH) {
            const uint32_t bo = (uint32_t)((c + 3) & 3) * BUFSZ;
            const size_t ka = (size_t)(c + 3) * 64;
            const size_t kb = (size_t)(c + 3) * 64 * NF;
#pragma unroll
            for (int i = 0; i < APT4; i++) CP16(adst[i] + bo, asrc[i] + ka);
#pragma unroll
            for (int i = 0; i < BPT4; i++) CP16(bdst[i] + bo, bsrc[i] + kb);
        }
        CP_COMMIT();

        const char* Ab = smc + (c & 3) * BUFSZ;
        const char* Bb = Ab + APL;

#pragma unroll
        for (int h = 0; h < 2; h++) {
            const int ks = h * 16;
            // B fragments (hi + lo planes): single lds.32 each (R15-proven)
            uint32_t bhf[NI][2], blf[NI][2];
#pragma unroll
            for (int ni = 0; ni < NI; ni++) {
                uint32_t w0 = (uint32_t)((ks >> 1) + tg) * BROWW + wn + ni * 8 + g;
                uint32_t w1 = w0 + 4 * BROWW;
                bhf[ni][0] = *(const uint32_t*)(Bb + 4 * w0);
                bhf[ni][1] = *(const uint32_t*)(Bb + 4 * w1);
                blf[ni][0] = *(const uint32_t*)(Bb + BPLP + 4 * w0);
                blf[ni][1] = *(const uint32_t*)(Bb + BPLP + 4 * w1);
            }
            // A fragments (single plane, R15-proven)
            uint32_t af[MI][4];
#pragma unroll
            for (int mi = 0; mi < MI; mi++) {
                uint32_t base = (uint32_t)(wm + mi * 16 + g) * ROWB + ks * 2 + 4 * tg;
                af[mi][0] = *(const uint32_t*)(Ab + base);
                af[mi][1] = *(const uint32_t*)(Ab + base + 8 * ROWB);
                af[mi][2] = *(const uint32_t*)(Ab + base + 16);
                af[mi][3] = *(const uint32_t*)(Ab + base + 8 * ROWB + 16);
            }
#pragma unroll
            for (int mi = 0; mi < MI; mi++)
#pragma unroll
                for (int ni = 0; ni < NI; ni++) {
                    MMA_FP16(acc[mi][ni], af[mi], bhf[ni]);   // A*Bh
                    MMA_FP16(acc[mi][ni], af[mi], blf[ni]);   // A*Bl
                }
        }
    }

    // ----------------------------- epilogue --------------------------------
    const float* bs = bias + (size_t)s * NF + n0;
    const float* gb = gbias + n0;
#pragma unroll
    for (int mi = 0; mi < MI; mi++) {
        const int rbase = wm + mi * 16 + g;
#pragma unroll
        for (int ni = 0; ni < NI; ni++) {
            const int c0 = wn + ni * 8 + 2 * tg;
            const float bv0 = bs[c0] + gb[c0];
            const float bv1 = bs[c0 + 1] + gb[c0 + 1];
#pragma unroll
            for (int half = 0; half < 2; half++) {
                const int r = rbase + half * 8;
                if (r < rows) {
                    float v0 = acc[mi][ni][half * 2 + 0] + bv0;
                    float v1 = acc[mi][ni][half * 2 + 1] + bv1;
                    if (RELU) { v0 = fmaxf(v0, 0.f); v1 = fmaxf(v1, 0.f); }
                    const int prow = off + m0 + r;
                    if (LAYER == 2) {
                        const int orow = g_perm[prow];
                        *(float2*)(fout + (size_t)orow * NF + n0 + c0) = make_float2(v0, v1);
                    } else {
                        // fp16 rn after relu == relu after rn (sign/zero preserved)
                        *(uint32_t*)(Aout + (size_t)prow * NF + n0 + c0) =
                            pack2h(__float2half_rn(v0), __float2half_rn(v1));
                    }
                }
            }
        }
    }
}

// ---------------------------------------------------------------------------
extern "C" void kernel_launch(void* const* d_in, const int* in_sizes, int n_in,
                              void* d_out, int out_size) {
    const float* x     = (const float*)d_in[0];
    const int*   scene = (const int*)d_in[1];   // int32 or int64, auto-detected
    const float* W0  = (const float*)d_in[2];
    const float* b0  = (const float*)d_in[3];
    const float* gW0 = (const float*)d_in[4];
    const float* gb0 = (const float*)d_in[5];
    const float* W1  = (const float*)d_in[6];
    const float* b1  = (const float*)d_in[7];
    const float* gW1 = (const float*)d_in[8];
    const float* gb1 = (const float*)d_in[9];
    const float* W2  = (const float*)d_in[10];
    const float* b2  = (const float*)d_in[11];
    const float* gW2 = (const float*)d_in[12];
    const float* gb2 = (const float*)d_in[13];
    float* out = (float*)d_out;

    const int B = in_sizes[1];
    const int lt128 = (B + 127) / 128 + NS - 1;
    const int lt64  = (B + 63) / 64 + NS - 1;

    // smem: 4 buffers: L0/L1: 4*(128*80 + 2*16*(128+8)*4) = 110592
    //                  L2:    4*(64*80  + 2*16*(64+8)*4)  = 57344
    const int SM_L01 = 4 * (128 * 80 + 2 * 16 * (128 + 8) * 4);
    const int SM_L2  = 4 * (64 * 80 + 2 * 16 * (64 + 8) * 4);

    cudaFuncSetAttribute(k_gemm<0, D0, D1, 128, 128, true >,
                         cudaFuncAttributeMaxDynamicSharedMemorySize, SM_L01);
    cudaFuncSetAttribute(k_gemm<1, D1, D2, 128, 128, true >,
                         cudaFuncAttributeMaxDynamicSharedMemorySize, SM_L01);
    cudaFuncSetAttribute(k_gemm<2, D2, D3, 64, 64, false>,
                         cudaFuncAttributeMaxDynamicSharedMemorySize, SM_L2);

    k_splitw<<<512, 256>>>(W0, gW0, W1, gW1, W2, gW2);
    k_countscan<<<1, 256>>>(scene, B);
    k_scatter<<<(B + 255) / 256, 256>>>(scene, B);
    k_xcvt<<<(B * (D0 / 8) + 255) / 256, 256>>>(x, B);

    k_gemm<0, D0, D1, 128, 128, true ><<<dim3(lt128, D1 / 128), 256, SM_L01>>>(
        nullptr, b0, gb0, B);
    k_gemm<1, D1, D2, 128, 128, true ><<<dim3(lt128, D2 / 128), 256, SM_L01>>>(
        nullptr, b1, gb1, B);
    k_gemm<2, D2, D3, 64, 64, false><<<dim3(lt64, 1), 256, SM_L2>>>(
        out, b2, gb2, B);
}

// round 17
// speedup vs baseline: 1.5345x; 1.0208x over previous
#include <cuda_runtime.h>
#include <cuda_fp16.h>
#include <cstdint>

// ---------------------------------------------------------------------------
// STARDNN on GB300. R17 = R16 (125.4us proven) + two scoped changes:
//  (1) k_xcvt + k_splitw fused into k_prep (one launch; gemm0 back at slot #4)
//  (2) A fragments via ldmatrix.x4 (16 lds.32 -> 4 ldmatrix per k16 step).
// Numerics bit-identical to R15/R16 -> rel_err must stay 3.647099e-4.
// ---------------------------------------------------------------------------

#define NS    7
#define MAXB  16384
#define D0    512
#define D1    512
#define D2    256
#define D3    64

// ------------------------- device scratch (no allocs) ----------------------
__device__ int g_count[NS];
__device__ int g_offset[NS];
__device__ int g_cursor[NS];
__device__ int g_tile128[NS + 1];
__device__ int g_tile64[NS + 1];
__device__ int g_perm[MAXB];
// activations fp16, permuted row order
__device__ __align__(256) __half g_ax[MAXB * D0];
__device__ __align__(256) __half g_a1[MAXB * D1];
__device__ __align__(256) __half g_a2[MAXB * D2];
// weights fp16 hi/lo, k-pair packed words [s][K/2][N]
__device__ __align__(256) uint32_t g_Bh0[NS * (D0 / 2) * D1], g_Bl0[NS * (D0 / 2) * D1];
__device__ __align__(256) uint32_t g_Bh1[NS * (D1 / 2) * D2], g_Bl1[NS * (D1 / 2) * D2];
__device__ __align__(256) uint32_t g_Bh2[NS * (D2 / 2) * D3], g_Bl2[NS * (D2 / 2) * D3];

// ------------------------------ helpers ------------------------------------
__device__ __forceinline__ uint32_t smem_u32(const void* p) {
    uint32_t a;
    asm("{ .reg .u64 t; cvta.to.shared.u64 t, %1; cvt.u32.u64 %0, t; }" : "=r"(a) : "l"(p));
    return a;
}

#define CP16(dst, src) \
    asm volatile("cp.async.cg.shared.global [%0], [%1], 16;" :: "r"(dst), "l"(src))
#define CP_COMMIT() asm volatile("cp.async.commit_group;" ::: "memory")
#define CP_WAIT2()  asm volatile("cp.async.wait_group 2;" ::: "memory")

#define MMA_FP16(d, a, b) \
    asm volatile("mma.sync.aligned.m16n8k16.row.col.f32.f16.f16.f32 " \
                 "{%0,%1,%2,%3}, {%4,%5,%6,%7}, {%8,%9}, {%0,%1,%2,%3};" \
                 : "+f"((d)[0]), "+f"((d)[1]), "+f"((d)[2]), "+f"((d)[3]) \
                 : "r"((a)[0]), "r"((a)[1]), "r"((a)[2]), "r"((a)[3]), \
                   "r"((b)[0]), "r"((b)[1]))

#define LDSM_X4(r, addr) \
    asm volatile("ldmatrix.sync.aligned.m8n8.x4.shared.b16 {%0,%1,%2,%3}, [%4];" \
                 : "=r"((r)[0]), "=r"((r)[1]), "=r"((r)[2]), "=r"((r)[3]) : "r"(addr))

__device__ __forceinline__ uint32_t pack2h(__half a, __half b) {
    union { __half h[2]; uint32_t u; } t;
    t.h[0] = a; t.h[1] = b;
    return t.u;
}

// ------------------------------ bucketing (proven) -------------------------
__device__ __forceinline__ int scene_at(const int* __restrict__ p, int b, bool is64) {
    int v = is64 ? p[2 * b] : p[b];
    int s = v - 1;
    return (s < 0) ? 0 : (s >= NS ? NS - 1 : s);
}

__global__ __launch_bounds__(256) void k_countscan(const int* __restrict__ scene, int B) {
    __shared__ int hist[NS];
    if (threadIdx.x < NS) hist[threadIdx.x] = 0;
    __syncthreads();
    bool is64 = (scene[1] == 0);
    for (int b = threadIdx.x; b < B; b += 256)
        atomicAdd(&hist[scene_at(scene, b, is64)], 1);
    __syncthreads();
    if (threadIdx.x == 0) {
        int off = 0, t128 = 0, t64 = 0;
        for (int s = 0; s < NS; s++) {
            int c = hist[s];
            g_count[s] = c;
            g_offset[s] = off;
            g_cursor[s] = off;
            g_tile128[s] = t128;
            g_tile64[s] = t64;
            off += c;
            t128 += (c + 127) >> 7;
            t64  += (c + 63) >> 6;
        }
        g_tile128[NS] = t128;
        g_tile64[NS] = t64;
    }
}

__global__ void k_scatter(const int* __restrict__ scene, int B) {
    int b = blockIdx.x * blockDim.x + threadIdx.x;
    if (b < B) {
        bool is64 = (scene[1] == 0);
        int s = scene_at(scene, b, is64);
        int pos = atomicAdd(&g_cursor[s], 1);
        g_perm[pos] = b;
    }
}

// fused prep: (phase 1) gather+convert x -> fp16; (phase 2) weight split
__device__ void splitw_sec(const float* __restrict__ W, const float* __restrict__ gW,
                           uint32_t* __restrict__ dh, uint32_t* __restrict__ dl,
                           int KD, int ND, int t, int stride) {
    const int TOT = (KD / 2) * ND;
    for (int j = t; j < TOT; j += stride) {
        int k2 = j / ND, n = j % ND;
        size_t i0 = (size_t)(2 * k2) * ND + n;
        size_t i1 = i0 + ND;
        float ga = gW[i0], gb = gW[i1];
        for (int s = 0; s < NS; s++) {
            size_t wb = (size_t)s * KD * ND;
            float w0 = W[wb + i0] * ga;
            float w1 = W[wb + i1] * gb;
            __half h0 = __float2half_rn(w0), h1 = __float2half_rn(w1);
            dh[(size_t)s * TOT + j] = pack2h(h0, h1);
            dl[(size_t)s * TOT + j] = pack2h(__float2half_rn(w0 - __half2float(h0)),
                                             __float2half_rn(w1 - __half2float(h1)));
        }
    }
}

__global__ __launch_bounds__(256) void k_prep(
    const float* __restrict__ x, int B,
    const float* __restrict__ W0, const float* __restrict__ gW0,
    const float* __restrict__ W1, const float* __restrict__ gW1,
    const float* __restrict__ W2, const float* __restrict__ gW2) {
    int t = blockIdx.x * blockDim.x + threadIdx.x;
    int stride = gridDim.x * blockDim.x;
    // phase 1: x gather + fp16 convert (needs perm; scatter ran before)
    int xtot = B * (D0 / 8);
    for (int i = t; i < xtot; i += stride) {
        int p = i / (D0 / 8), j = (i % (D0 / 8)) * 8;
        int src = g_perm[p];
        const float4* sp = (const float4*)(x + (size_t)src * D0 + j);
        float4 v0 = sp[0], v1 = sp[1];
        uint4 o;
        o.x = pack2h(__float2half_rn(v0.x), __float2half_rn(v0.y));
        o.y = pack2h(__float2half_rn(v0.z), __float2half_rn(v0.w));
        o.z = pack2h(__float2half_rn(v1.x), __float2half_rn(v1.y));
        o.w = pack2h(__float2half_rn(v1.z), __float2half_rn(v1.w));
        *(uint4*)(g_ax + (size_t)p * D0 + j) = o;
    }
    // phase 2: weight split (independent of perm)
    splitw_sec(W0, gW0, g_Bh0, g_Bl0, D0, D1, t, stride);
    splitw_sec(W1, gW1, g_Bh1, g_Bl1, D1, D2, t, stride);
    splitw_sec(W2, gW2, g_Bh2, g_Bl2, D2, D3, t, stride);
}

// ------------------------------ mma GEMM -----------------------------------
// CTA: BM x BN tile. K in chunks of 32; 4-deep cp.async pipeline.
// A smem: fp16 [BM][32] rows, ROWB=80; fragments via ldmatrix.x4.
// B smem: fp16 hi/lo k-pair planes; fragments = single lds.32 (proven).
template <int LAYER, int K, int NF, int BM, int BN, bool RELU>
__global__ __launch_bounds__(256, 2) void k_gemm(float* __restrict__ fout,
                                                 const float* __restrict__ bias,
                                                 const float* __restrict__ gbias,
                                                 int B) {
    constexpr int MI = BM / 2 / 16;
    constexpr int NI = BN / 4 / 8;
    constexpr int NCH = K / 32;
    constexpr int ROWB = 80;
    constexpr int APL = BM * ROWB;
    constexpr int BROWW = BN + 8;
    constexpr int BROWB = BROWW * 4;
    constexpr int BPLP = 16 * BROWB;
    constexpr int BUFSZ = APL + 2 * BPLP;
    constexpr int APT4 = BM * 4 / 256;
    constexpr int BCH  = 2 * 16 * (BN / 4);
    constexpr int BPT4 = BCH / 256;

    extern __shared__ char smc[];
    const uint32_t sb = smem_u32(smc);

    const int* tstart = (BM == 128) ? g_tile128 : g_tile64;
    const int t = blockIdx.x;
    if (t >= tstart[NS]) return;
    int s = 0;
    while (tstart[s + 1] <= t) s++;
    const int m0   = (t - tstart[s]) * BM;
    const int cnt  = g_count[s];
    const int off  = g_offset[s];
    const int rows = min(BM, cnt - m0);
    const int n0   = blockIdx.y * BN;
    const int tid  = threadIdx.x;

    const __half* Ain = (LAYER == 0) ? g_ax : (LAYER == 1 ? g_a1 : g_a2);
    const uint32_t* Bh = (LAYER == 0) ? g_Bh0 : (LAYER == 1 ? g_Bh1 : g_Bh2);
    const uint32_t* Bl = (LAYER == 0) ? g_Bl0 : (LAYER == 1 ? g_Bl1 : g_Bl2);
    __half* Aout = (LAYER == 0) ? g_a1 : g_a2;

    // ---- cp.async descriptors (chunk-invariant; only k advances) ----
    const char* asrc[APT4];
    uint32_t adst[APT4];
#pragma unroll
    for (int i = 0; i < APT4; i++) {
        int idx = tid + i * 256;
        int row = idx >> 2, q = idx & 3;
        int pr = off + m0 + ((row < rows) ? row : 0);
        if (pr > B - 1) pr = B - 1;
        asrc[i] = (const char*)(Ain + (size_t)pr * K) + q * 16;
        adst[i] = sb + (uint32_t)row * ROWB + q * 16;
    }
    const char* bsrc[BPT4];
    uint32_t bdst[BPT4];
#pragma unroll
    for (int i = 0; i < BPT4; i++) {
        int idx = tid + i * 256;
        int plane = idx / (BCH / 2);
        int rem = idx % (BCH / 2);
        int krow = rem / (BN / 4), q = rem % (BN / 4);
        const uint32_t* P = plane ? Bl : Bh;
        bsrc[i] = (const char*)(P + (size_t)s * (K / 2) * NF + (size_t)krow * NF + n0 + q * 4);
        bdst[i] = sb + APL + (uint32_t)plane * BPLP + (uint32_t)krow * BROWB + q * 16;
    }

    const int lane = tid & 31, w = tid >> 5;
    const int wm = (w >> 2) * (BM / 2);
    const int wn = (w & 3) * (BN / 4);
    const int g  = lane >> 2, tg = lane & 3;
    // ldmatrix.x4 lane addressing for A: lanes 0-15 -> rows (lane&15) k-lo,
    // lanes 16-31 -> same rows +16B (k-hi). Output regs = .row A fragment.
    const int arow  = wm + (lane & 15);
    const int acolb = (lane >> 4) * 16;

    float acc[MI][NI][4];
#pragma unroll
    for (int mi = 0; mi < MI; mi++)
#pragma unroll
        for (int ni = 0; ni < NI; ni++)
#pragma unroll
            for (int e = 0; e < 4; e++) acc[mi][ni][e] = 0.f;

    // ---- prologue: issue chunks 0..2 ----
#pragma unroll
    for (int p = 0; p < 3; p++) {
        if (p < NCH) {
            const uint32_t bo = (uint32_t)p * BUFSZ;
#pragma unroll
            for (int i = 0; i < APT4; i++) CP16(adst[i] + bo, asrc[i] + (size_t)p * 64);
#pragma unroll
            for (int i = 0; i < BPT4; i++) CP16(bdst[i] + bo, bsrc[i] + (size_t)p * 64 * NF);
        }
        CP_COMMIT();
    }

    for (int c = 0; c < NCH; c++) {
        CP_WAIT2();
        __syncthreads();

        if (c + 3 < NCH) {
            const uint32_t bo = (uint32_t)((c + 3) & 3) * BUFSZ;
            const size_t ka = (size_t)(c + 3) * 64;
            const size_t kb = (size_t)(c + 3) * 64 * NF;
#pragma unroll
            for (int i = 0; i < APT4; i++) CP16(adst[i] + bo, asrc[i] + ka);
#pragma unroll
            for (int i = 0; i < BPT4; i++) CP16(bdst[i] + bo, bsrc[i] + kb);
        }
        CP_COMMIT();

        const uint32_t Abu = sb + (uint32_t)(c & 3) * BUFSZ;
        const char* Bb = smc + (c & 3) * BUFSZ + APL;

#pragma unroll
        for (int h = 0; h < 2; h++) {
            const int ks = h * 16;
            // B fragments (hi + lo planes): single lds.32 each (proven)
            uint32_t bhf[NI][2], blf[NI][2];
#pragma unroll
            for (int ni = 0; ni < NI; ni++) {
                uint32_t w0 = (uint32_t)((ks >> 1) + tg) * BROWW + wn + ni * 8 + g;
                uint32_t w1 = w0 + 4 * BROWW;
                bhf[ni][0] = *(const uint32_t*)(Bb + 4 * w0);
                bhf[ni][1] = *(const uint32_t*)(Bb + 4 * w1);
                blf[ni][0] = *(const uint32_t*)(Bb + BPLP + 4 * w0);
                blf[ni][1] = *(const uint32_t*)(Bb + BPLP + 4 * w1);
            }
            // A fragments via ldmatrix.x4 (one per m16 tile)
            uint32_t af[MI][4];
#pragma unroll
            for (int mi = 0; mi < MI; mi++) {
                uint32_t aaddr = Abu + (uint32_t)(arow + mi * 16) * ROWB + ks * 2 + acolb;
                LDSM_X4(af[mi], aaddr);
            }
#pragma unroll
            for (int mi = 0; mi < MI; mi++)
#pragma unroll
                for (int ni = 0; ni < NI; ni++) {
                    MMA_FP16(acc[mi][ni], af[mi], bhf[ni]);   // A*Bh
                    MMA_FP16(acc[mi][ni], af[mi], blf[ni]);   // A*Bl
                }
        }
    }

    // ----------------------------- epilogue --------------------------------
    const float* bs = bias + (size_t)s * NF + n0;
    const float* gb = gbias + n0;
#pragma unroll
    for (int mi = 0; mi < MI; mi++) {
        const int rbase = wm + mi * 16 + g;
#pragma unroll
        for (int ni = 0; ni < NI; ni++) {
            const int c0 = wn + ni * 8 + 2 * tg;
            const float bv0 = bs[c0] + gb[c0];
            const float bv1 = bs[c0 + 1] + gb[c0 + 1];
#pragma unroll
            for (int half = 0; half < 2; half++) {
                const int r = rbase + half * 8;
                if (r < rows) {
                    float v0 = acc[mi][ni][half * 2 + 0] + bv0;
                    float v1 = acc[mi][ni][half * 2 + 1] + bv1;
                    if (RELU) { v0 = fmaxf(v0, 0.f); v1 = fmaxf(v1, 0.f); }
                    const int prow = off + m0 + r;
                    if (LAYER == 2) {
                        const int orow = g_perm[prow];
                        *(float2*)(fout + (size_t)orow * NF + n0 + c0) = make_float2(v0, v1);
                    } else {
                        *(uint32_t*)(Aout + (size_t)prow * NF + n0 + c0) =
                            pack2h(__float2half_rn(v0), __float2half_rn(v1));
                    }
                }
            }
        }
    }
}

// ---------------------------------------------------------------------------
extern "C" void kernel_launch(void* const* d_in, const int* in_sizes, int n_in,
                              void* d_out, int out_size) {
    const float* x     = (const float*)d_in[0];
    const int*   scene = (const int*)d_in[1];   // int32 or int64, auto-detected
    const float* W0  = (const float*)d_in[2];
    const float* b0  = (const float*)d_in[3];
    const float* gW0 = (const float*)d_in[4];
    const float* gb0 = (const float*)d_in[5];
    const float* W1  = (const float*)d_in[6];
    const float* b1  = (const float*)d_in[7];
    const float* gW1 = (const float*)d_in[8];
    const float* gb1 = (const float*)d_in[9];
    const float* W2  = (const float*)d_in[10];
    const float* b2  = (const float*)d_in[11];
    const float* gW2 = (const float*)d_in[12];
    const float* gb2 = (const float*)d_in[13];
    float* out = (float*)d_out;

    const int B = in_sizes[1];
    const int lt128 = (B + 127) / 128 + NS - 1;
    const int lt64  = (B + 63) / 64 + NS - 1;

    const int SM_L01 = 4 * (128 * 80 + 2 * 16 * (128 + 8) * 4);   // 110592
    const int SM_L2  = 4 * (64 * 80 + 2 * 16 * (64 + 8) * 4);     // 57344

    cudaFuncSetAttribute(k_gemm<0, D0, D1, 128, 128, true >,
                         cudaFuncAttributeMaxDynamicSharedMemorySize, SM_L01);
    cudaFuncSetAttribute(k_gemm<1, D1, D2, 128, 128, true >,
                         cudaFuncAttributeMaxDynamicSharedMemorySize, SM_L01);
    cudaFuncSetAttribute(k_gemm<2, D2, D3, 64, 64, false>,
                         cudaFuncAttributeMaxDynamicSharedMemorySize, SM_L2);

    // launch order: countscan, scatter, prep(fused), gemm0 (= ncu slot #4)
    k_countscan<<<1, 256>>>(scene, B);
    k_scatter<<<(B + 255) / 256, 256>>>(scene, B);
    k_prep<<<2048, 256>>>(x, B, W0, gW0, W1, gW1, W2, gW2);

    k_gemm<0, D0, D1, 128, 128, true ><<<dim3(lt128, D1 / 128), 256, SM_L01>>>(
        nullptr, b0, gb0, B);
    k_gemm<1, D1, D2, 128, 128, true ><<<dim3(lt128, D2 / 128), 256, SM_L01>>>(
        nullptr, b1, gb1, B);
    k_gemm<2, D2, D3, 64, 64, false><<<dim3(lt64, 1), 256, SM_L2>>>(
        out, b2, gb2, B);
}